// round 1
// baseline (speedup 1.0000x reference)
#include <cuda_runtime.h>

#define D 64
#define MAXN 100000
#define MAXE 1600000

// ---------------- static scratch (no allocations allowed) ----------------
__device__ int    g_rowptr[MAXN + 1];
__device__ int    g_cursor[MAXN];
__device__ int    g_ssrc[MAXE];          // src ids, dst-sorted
__device__ float4 g_sea[MAXE];           // edge_attr, dst-sorted
__device__ float  g_X[MAXN * D];         // current node features
__device__ float  g_H[MAXN * D];         // Wx @ x per node
__device__ float  g_Y[MAXN * D];         // x + agg
__device__ int    g_bsums[256];
__device__ int    g_boffs[256];

__device__ __forceinline__ float*       bufw(int s) { return s == 0 ? g_X : (s == 1 ? g_H : g_Y); }
__device__ __forceinline__ const float* bufr(int s) { return s == 0 ? g_X : (s == 1 ? g_H : g_Y); }

// ---------------- CSR build ----------------
__global__ void k_zero(int N) {
    int i = blockIdx.x * blockDim.x + threadIdx.x;
    if (i < N) g_cursor[i] = 0;
}

__global__ void k_hist(const int* __restrict__ dst, int E) {
    int e = blockIdx.x * blockDim.x + threadIdx.x;
    if (e < E) atomicAdd(&g_cursor[dst[e]], 1);
}

// block of 256 threads scans 1024 counts -> local-exclusive prefixes + block sum
__global__ void k_scan1(int N) {
    __shared__ int s[256];
    int t = threadIdx.x;
    int base = blockIdx.x * 1024 + t * 4;
    int v0 = (base + 0 < N) ? g_cursor[base + 0] : 0;
    int v1 = (base + 1 < N) ? g_cursor[base + 1] : 0;
    int v2 = (base + 2 < N) ? g_cursor[base + 2] : 0;
    int v3 = (base + 3 < N) ? g_cursor[base + 3] : 0;
    int tsum = v0 + v1 + v2 + v3;
    s[t] = tsum;
    __syncthreads();
    for (int off = 1; off < 256; off <<= 1) {
        int x = (t >= off) ? s[t - off] : 0;
        __syncthreads();
        s[t] += x;
        __syncthreads();
    }
    int excl = s[t] - tsum;
    if (t == 255) g_bsums[blockIdx.x] = s[255];
    if (base + 0 < N) g_rowptr[base + 0] = excl;
    if (base + 1 < N) g_rowptr[base + 1] = excl + v0;
    if (base + 2 < N) g_rowptr[base + 2] = excl + v0 + v1;
    if (base + 3 < N) g_rowptr[base + 3] = excl + v0 + v1 + v2;
}

__global__ void k_scan2(int nb) {
    __shared__ int s[256];
    int t = threadIdx.x;
    int v = (t < nb) ? g_bsums[t] : 0;
    s[t] = v;
    __syncthreads();
    for (int off = 1; off < 256; off <<= 1) {
        int x = (t >= off) ? s[t - off] : 0;
        __syncthreads();
        s[t] += x;
        __syncthreads();
    }
    g_boffs[t] = s[t] - v;
}

__global__ void k_scan3(int N, int E) {
    int i = blockIdx.x * blockDim.x + threadIdx.x;
    if (i < N) {
        int r = g_rowptr[i] + g_boffs[i >> 10];
        g_rowptr[i] = r;
        g_cursor[i] = r;
    }
    if (i == N) g_rowptr[N] = E;
}

__global__ void k_scatter(const int* __restrict__ src, const int* __restrict__ dst,
                          const float* __restrict__ ea, int E) {
    int e = blockIdx.x * blockDim.x + threadIdx.x;
    if (e >= E) return;
    int p = atomicAdd(&g_cursor[dst[e]], 1);
    g_ssrc[p] = src[e];
    g_sea[p]  = *reinterpret_cast<const float4*>(ea + 4 * (size_t)e);
}

// ---------------- node feature kernels ----------------
__global__ void k_embed(const int* __restrict__ ids, const float* __restrict__ emb, int N) {
    int i = blockIdx.x * blockDim.x + threadIdx.x;
    if (i < N * D) {
        int n = i >> 6;
        g_X[i] = emb[ids[n] * D + (i & 63)];
    }
}

// out[n] = (relu?)(W(:,0:63) @ in[n] + bias). warp-per-node; W in smem (transposed).
__global__ void __launch_bounds__(256) k_matvec(int insel, int outsel,
                                                const float* __restrict__ W, int wstride,
                                                const float* __restrict__ bias, int relu, int N) {
    __shared__ float Ws[D * D];   // Ws[j*64 + i] = W[i][j]
    __shared__ float sb[D];
    const float* in = bufr(insel);
    float* out = bufw(outsel);
    int t = threadIdx.x;
    for (int idx = t; idx < D * D; idx += 256) {
        int i = idx & 63, j = idx >> 6;
        Ws[idx] = W[i * wstride + j];
    }
    if (t < D) sb[t] = bias ? bias[t] : 0.0f;
    __syncthreads();

    int lane = t & 31;
    int gw = (blockIdx.x * 256 + t) >> 5;
    int nw = (gridDim.x * 256) >> 5;
    for (int n = gw; n < N; n += nw) {
        float2 xv = *reinterpret_cast<const float2*>(in + n * D + 2 * lane);
        float ax = 0.0f, ay = 0.0f;
#pragma unroll
        for (int jj = 0; jj < 32; jj++) {
            float xa = __shfl_sync(0xffffffffu, xv.x, jj);
            float xb = __shfl_sync(0xffffffffu, xv.y, jj);
            float2 w0 = *reinterpret_cast<const float2*>(&Ws[(2 * jj) * D + 2 * lane]);
            float2 w1 = *reinterpret_cast<const float2*>(&Ws[(2 * jj + 1) * D + 2 * lane]);
            ax = fmaf(xa, w0.x, ax);
            ay = fmaf(xa, w0.y, ay);
            ax = fmaf(xb, w1.x, ax);
            ay = fmaf(xb, w1.y, ay);
        }
        ax += sb[2 * lane];
        ay += sb[2 * lane + 1];
        if (relu) { ax = fmaxf(ax, 0.0f); ay = fmaxf(ay, 0.0f); }
        *reinterpret_cast<float2*>(out + n * D + 2 * lane) = make_float2(ax, ay);
    }
}

// Y[n] = X[n] + sum_{e: dst=n} relu(H[src_e] + We @ ea_e + b). warp-per-node gather.
__global__ void __launch_bounds__(256) k_agg(const float* __restrict__ Wm,
                                             const float* __restrict__ bm, int N) {
    int t = threadIdx.x, lane = t & 31;
    // We rows for this lane's two output dims (Wm is (64,68) row-major; cols 64..67)
    float4 wa = *reinterpret_cast<const float4*>(Wm + (2 * lane) * 68 + 64);
    float4 wb = *reinterpret_cast<const float4*>(Wm + (2 * lane + 1) * 68 + 64);
    float b0 = bm[2 * lane], b1 = bm[2 * lane + 1];

    int gw = (blockIdx.x * 256 + t) >> 5;
    int nw = (gridDim.x * 256) >> 5;
    for (int n = gw; n < N; n += nw) {
        float2 acc = *reinterpret_cast<const float2*>(g_X + n * D + 2 * lane);
        int k0 = g_rowptr[n], k1 = g_rowptr[n + 1];
#pragma unroll 4
        for (int k = k0; k < k1; k++) {
            int s = g_ssrc[k];
            float4 ea = g_sea[k];
            float2 hv = *reinterpret_cast<const float2*>(g_H + s * D + 2 * lane);
            float m0 = fmaf(wa.x, ea.x, fmaf(wa.y, ea.y, fmaf(wa.z, ea.z, fmaf(wa.w, ea.w, b0 + hv.x))));
            float m1 = fmaf(wb.x, ea.x, fmaf(wb.y, ea.y, fmaf(wb.z, ea.z, fmaf(wb.w, ea.w, b1 + hv.y))));
            acc.x += fmaxf(m0, 0.0f);
            acc.y += fmaxf(m1, 0.0f);
        }
        *reinterpret_cast<float2*>(g_Y + n * D + 2 * lane) = acc;
    }
}

// ---------------- mean over nodes ----------------
__global__ void k_zero_out(float* out) {
    if (threadIdx.x < D) out[threadIdx.x] = 0.0f;
}

__global__ void __launch_bounds__(256) k_mean(float* __restrict__ out, int N) {
    __shared__ float sm[256];
    int t = threadIdx.x;
    int d = t & 63;
    float acc = 0.0f;
    for (int n = blockIdx.x * 4 + (t >> 6); n < N; n += gridDim.x * 4)
        acc += g_X[n * D + d];
    sm[t] = acc;
    __syncthreads();
    if (t < 128) sm[t] += sm[t + 128];
    __syncthreads();
    if (t < 64) {
        float v = sm[t] + sm[t + 64];
        atomicAdd(&out[t], v * (1.0f / (float)N));
    }
}

// ---------------- launch ----------------
extern "C" void kernel_launch(void* const* d_in, const int* in_sizes, int n_in,
                              void* d_out, int out_size) {
    const int*   x_ids = (const int*)d_in[0];
    const int*   eidx  = (const int*)d_in[1];
    const float* eattr = (const float*)d_in[2];
    const float* emb   = (const float*)d_in[3];
    const float* W1  = (const float*)d_in[4];
    const float* b1  = (const float*)d_in[5];
    const float* Wu1 = (const float*)d_in[6];
    const float* bu1 = (const float*)d_in[7];
    const float* W2  = (const float*)d_in[8];
    const float* b2  = (const float*)d_in[9];
    const float* Wu2 = (const float*)d_in[10];
    const float* bu2 = (const float*)d_in[11];
    float* out = (float*)d_out;

    int N = in_sizes[0];
    int E = in_sizes[1] / 2;
    const int* src = eidx;
    const int* dst = eidx + E;

    // CSR build (dst-sorted edges)
    k_zero<<<(N + 255) / 256, 256>>>(N);
    k_hist<<<(E + 255) / 256, 256>>>(dst, E);
    int nb = (N + 1023) / 1024;
    k_scan1<<<nb, 256>>>(N);
    k_scan2<<<1, 256>>>(nb);
    k_scan3<<<(N + 1 + 255) / 256, 256>>>(N, E);
    k_scatter<<<(E + 255) / 256, 256>>>(src, dst, eattr, E);

    // x0 = emb[x_ids]
    k_embed<<<(N * D + 255) / 256, 256>>>(x_ids, emb, N);

    const int MVG = 1184;   // matvec grid (warp-per-node, grid-stride)
    const int AGG = 2048;   // agg grid

    // round 1: H = X @ Wx1^T ; Y = X + agg(relu(H[src] + We1@ea + b1)) ; X = relu(Y @ Wu1^T + bu1)
    k_matvec<<<MVG, 256>>>(0, 1, W1, 68, (const float*)nullptr, 0, N);
    k_agg<<<AGG, 256>>>(W1, b1, N);
    k_matvec<<<MVG, 256>>>(2, 0, Wu1, 64, bu1, 1, N);

    // round 2
    k_matvec<<<MVG, 256>>>(0, 1, W2, 68, (const float*)nullptr, 0, N);
    k_agg<<<AGG, 256>>>(W2, b2, N);
    k_matvec<<<MVG, 256>>>(2, 0, Wu2, 64, bu2, 1, N);

    // out = mean(X, axis=0)
    k_zero_out<<<1, 64>>>(out);
    k_mean<<<512, 256>>>(out, N);
}

// round 3
// speedup vs baseline: 1.5364x; 1.5364x over previous
#include <cuda_runtime.h>

#define D 64
#define MAXN 100000
#define MAXE 1600000
#define MAXV 1024

// ---------------- static scratch ----------------
__device__ int    g_rowptr[MAXN + 1];
__device__ int    g_cursor[MAXN];
__device__ int    g_ssrc[MAXE];          // src ids, dst-sorted
__device__ float4 g_sea[MAXE];           // edge_attr, dst-sorted
__device__ float  g_X[MAXN * D];         // current node features
__device__ float  g_H[MAXN * D];         // Wx @ x (+ b) per node
__device__ float  g_Y[MAXN * D];         // x + agg
__device__ float  g_embH[MAXV * D];      // emb @ Wx1^T + b1
__device__ int    g_bsums[256];
__device__ int    g_boffs[256];

// ---------------- init / CSR build ----------------
__global__ void k_init(float* out, int N) {
    int i = blockIdx.x * blockDim.x + threadIdx.x;
    if (i < N) g_cursor[i] = 0;
    if (i < 64) out[i] = 0.0f;
}

__global__ void k_hist(const int* __restrict__ dst, int E) {
    int e = blockIdx.x * blockDim.x + threadIdx.x;
    if (e < E) atomicAdd(&g_cursor[dst[e]], 1);
}

__global__ void k_scan1(int N) {
    __shared__ int s[256];
    int t = threadIdx.x;
    int base = blockIdx.x * 1024 + t * 4;
    int v0 = (base + 0 < N) ? g_cursor[base + 0] : 0;
    int v1 = (base + 1 < N) ? g_cursor[base + 1] : 0;
    int v2 = (base + 2 < N) ? g_cursor[base + 2] : 0;
    int v3 = (base + 3 < N) ? g_cursor[base + 3] : 0;
    int tsum = v0 + v1 + v2 + v3;
    s[t] = tsum;
    __syncthreads();
    for (int off = 1; off < 256; off <<= 1) {
        int x = (t >= off) ? s[t - off] : 0;
        __syncthreads();
        s[t] += x;
        __syncthreads();
    }
    int excl = s[t] - tsum;
    if (t == 255) g_bsums[blockIdx.x] = s[255];
    if (base + 0 < N) g_rowptr[base + 0] = excl;
    if (base + 1 < N) g_rowptr[base + 1] = excl + v0;
    if (base + 2 < N) g_rowptr[base + 2] = excl + v0 + v1;
    if (base + 3 < N) g_rowptr[base + 3] = excl + v0 + v1 + v2;
}

__global__ void k_scan2(int nb) {
    __shared__ int s[256];
    int t = threadIdx.x;
    int v = (t < nb) ? g_bsums[t] : 0;
    s[t] = v;
    __syncthreads();
    for (int off = 1; off < 256; off <<= 1) {
        int x = (t >= off) ? s[t - off] : 0;
        __syncthreads();
        s[t] += x;
        __syncthreads();
    }
    g_boffs[t] = s[t] - v;
}

__global__ void k_scan3(int N, int E) {
    int i = blockIdx.x * blockDim.x + threadIdx.x;
    if (i < N) {
        int r = g_rowptr[i] + g_boffs[i >> 10];
        g_rowptr[i] = r;
        g_cursor[i] = r;
    }
    if (i == N) g_rowptr[N] = E;
}

__global__ void k_scatter(const int* __restrict__ src, const int* __restrict__ dst,
                          const float* __restrict__ ea, int E) {
    int e = blockIdx.x * blockDim.x + threadIdx.x;
    if (e >= E) return;
    int p = atomicAdd(&g_cursor[dst[e]], 1);
    g_ssrc[p] = src[e];
    g_sea[p]  = *reinterpret_cast<const float4*>(ea + 4 * (size_t)e);
}

// ---------------- embH = emb @ Wx1^T + b1 (tiny: V x 64) ----------------
__global__ void k_embH(const float* __restrict__ emb, const float* __restrict__ W1,
                       const float* __restrict__ b1, int V) {
    int v = blockIdx.x, i = threadIdx.x;
    const float* er = emb + v * D;
    const float* wr = W1 + i * 68;
    float acc = b1[i];
#pragma unroll 16
    for (int j = 0; j < D; j++) acc = fmaf(er[j], wr[j], acc);
    g_embH[v * D + i] = acc;
}

// ---------------- X = emb[ids], H = embH[ids] ----------------
__global__ void k_gather(const int* __restrict__ ids, const float* __restrict__ emb, int N) {
    int i = blockIdx.x * blockDim.x + threadIdx.x;
    if (i < N * 16) {
        int n = i >> 4, c = i & 15;
        int id = ids[n];
        reinterpret_cast<float4*>(g_X)[i] = reinterpret_cast<const float4*>(emb)[id * 16 + c];
        reinterpret_cast<float4*>(g_H)[i] = reinterpret_cast<const float4*>(g_embH)[id * 16 + c];
    }
}

// ---------------- Y[n] = X[n] + sum relu(H[src] + We@ea)  (bias folded into H) ----------------
__global__ void __launch_bounds__(256) k_agg(const float* __restrict__ Wm, int N) {
    int t = threadIdx.x, lane = t & 31;
    float4 wa = *reinterpret_cast<const float4*>(Wm + (2 * lane) * 68 + 64);
    float4 wb = *reinterpret_cast<const float4*>(Wm + (2 * lane + 1) * 68 + 64);

    int gw = (blockIdx.x * 256 + t) >> 5;
    int nw = (gridDim.x * 256) >> 5;
    for (int n = gw; n < N; n += nw) {
        float2 acc = *reinterpret_cast<const float2*>(g_X + n * D + 2 * lane);
        int k0 = g_rowptr[n], k1 = g_rowptr[n + 1];
#pragma unroll 4
        for (int k = k0; k < k1; k++) {
            int s = g_ssrc[k];
            float4 ea = g_sea[k];
            float2 hv = *reinterpret_cast<const float2*>(g_H + s * D + 2 * lane);
            float m0 = fmaf(wa.x, ea.x, fmaf(wa.y, ea.y, fmaf(wa.z, ea.z, fmaf(wa.w, ea.w, hv.x))));
            float m1 = fmaf(wb.x, ea.x, fmaf(wb.y, ea.y, fmaf(wb.z, ea.z, fmaf(wb.w, ea.w, hv.y))));
            acc.x += fmaxf(m0, 0.0f);
            acc.y += fmaxf(m1, 0.0f);
        }
        *reinterpret_cast<float2*>(g_Y + n * D + 2 * lane) = acc;
    }
}

// ---------------- fused: X = relu(Y@Wu^T+bu); H = X@Wxn^T + bn  (4 nodes/warp) ----------------
__global__ void __launch_bounds__(256) k_upd(const float* __restrict__ Wu, const float* __restrict__ bu,
                                             const float* __restrict__ Wn, const float* __restrict__ bn,
                                             int N) {
    __shared__ float Wus[64 * 64];   // Wus[j*64 + i] = Wu[i][j]; stride 64 keeps float2 loads 8B-aligned
    __shared__ float Wns[64 * 64];
    int t = threadIdx.x;
    for (int idx = t; idx < 4096; idx += 256) {
        int i = idx >> 6, j = idx & 63;
        Wus[j * 64 + i] = Wu[i * 64 + j];
        Wns[j * 64 + i] = Wn[i * 68 + j];
    }
    __syncthreads();

    int lane = t & 31;
    float bu0 = bu[2 * lane], bu1 = bu[2 * lane + 1];
    float bn0 = bn[2 * lane], bn1 = bn[2 * lane + 1];

    int gw = (blockIdx.x * 256 + t) >> 5;
    int nw = (gridDim.x * 256) >> 5;
    int ng = (N + 3) >> 2;
    for (int g = gw; g < ng; g += nw) {
        int n0 = g * 4;
        float2 y[4];
#pragma unroll
        for (int n = 0; n < 4; n++) {
            int nn = n0 + n;
            y[n] = (nn < N) ? *reinterpret_cast<const float2*>(g_Y + nn * D + 2 * lane)
                            : make_float2(0.0f, 0.0f);
        }
        float2 a[4] = {{0,0},{0,0},{0,0},{0,0}};
#pragma unroll 8
        for (int jj = 0; jj < 32; jj++) {
            float2 w0 = *reinterpret_cast<const float2*>(&Wus[(2 * jj) * 64 + 2 * lane]);
            float2 w1 = *reinterpret_cast<const float2*>(&Wus[(2 * jj + 1) * 64 + 2 * lane]);
#pragma unroll
            for (int n = 0; n < 4; n++) {
                float xa = __shfl_sync(0xffffffffu, y[n].x, jj);
                float xb = __shfl_sync(0xffffffffu, y[n].y, jj);
                a[n].x = fmaf(xa, w0.x, fmaf(xb, w1.x, a[n].x));
                a[n].y = fmaf(xa, w0.y, fmaf(xb, w1.y, a[n].y));
            }
        }
#pragma unroll
        for (int n = 0; n < 4; n++) {
            a[n].x = fmaxf(a[n].x + bu0, 0.0f);
            a[n].y = fmaxf(a[n].y + bu1, 0.0f);
            int nn = n0 + n;
            if (nn < N) *reinterpret_cast<float2*>(g_X + nn * D + 2 * lane) = a[n];
        }
        float2 h[4] = {{0,0},{0,0},{0,0},{0,0}};
#pragma unroll 8
        for (int jj = 0; jj < 32; jj++) {
            float2 w0 = *reinterpret_cast<const float2*>(&Wns[(2 * jj) * 64 + 2 * lane]);
            float2 w1 = *reinterpret_cast<const float2*>(&Wns[(2 * jj + 1) * 64 + 2 * lane]);
#pragma unroll
            for (int n = 0; n < 4; n++) {
                float xa = __shfl_sync(0xffffffffu, a[n].x, jj);
                float xb = __shfl_sync(0xffffffffu, a[n].y, jj);
                h[n].x = fmaf(xa, w0.x, fmaf(xb, w1.x, h[n].x));
                h[n].y = fmaf(xa, w0.y, fmaf(xb, w1.y, h[n].y));
            }
        }
#pragma unroll
        for (int n = 0; n < 4; n++) {
            h[n].x += bn0;
            h[n].y += bn1;
            int nn = n0 + n;
            if (nn < N) *reinterpret_cast<float2*>(g_H + nn * D + 2 * lane) = h[n];
        }
    }
}

// ---------------- final: out += mean(relu(Y@Wu2^T+bu2)) ----------------
__global__ void __launch_bounds__(256) k_final(const float* __restrict__ Wu, const float* __restrict__ bu,
                                               float* __restrict__ out, int N) {
    __shared__ float Wus[64 * 64];
    __shared__ float sacc[64];
    int t = threadIdx.x;
    for (int idx = t; idx < 4096; idx += 256) {
        int i = idx >> 6, j = idx & 63;
        Wus[j * 64 + i] = Wu[i * 64 + j];
    }
    if (t < 64) sacc[t] = 0.0f;
    __syncthreads();

    int lane = t & 31;
    float bu0 = bu[2 * lane], bu1 = bu[2 * lane + 1];
    float2 tot = make_float2(0.0f, 0.0f);

    int gw = (blockIdx.x * 256 + t) >> 5;
    int nw = (gridDim.x * 256) >> 5;
    int ng = (N + 3) >> 2;
    for (int g = gw; g < ng; g += nw) {
        int n0 = g * 4;
        float2 y[4];
#pragma unroll
        for (int n = 0; n < 4; n++) {
            int nn = n0 + n;
            y[n] = (nn < N) ? *reinterpret_cast<const float2*>(g_Y + nn * D + 2 * lane)
                            : make_float2(0.0f, 0.0f);
        }
        float2 a[4] = {{0,0},{0,0},{0,0},{0,0}};
#pragma unroll 8
        for (int jj = 0; jj < 32; jj++) {
            float2 w0 = *reinterpret_cast<const float2*>(&Wus[(2 * jj) * 64 + 2 * lane]);
            float2 w1 = *reinterpret_cast<const float2*>(&Wus[(2 * jj + 1) * 64 + 2 * lane]);
#pragma unroll
            for (int n = 0; n < 4; n++) {
                float xa = __shfl_sync(0xffffffffu, y[n].x, jj);
                float xb = __shfl_sync(0xffffffffu, y[n].y, jj);
                a[n].x = fmaf(xa, w0.x, fmaf(xb, w1.x, a[n].x));
                a[n].y = fmaf(xa, w0.y, fmaf(xb, w1.y, a[n].y));
            }
        }
#pragma unroll
        for (int n = 0; n < 4; n++) {
            int nn = n0 + n;
            if (nn < N) {
                tot.x += fmaxf(a[n].x + bu0, 0.0f);
                tot.y += fmaxf(a[n].y + bu1, 0.0f);
            }
        }
    }
    atomicAdd(&sacc[2 * lane], tot.x);
    atomicAdd(&sacc[2 * lane + 1], tot.y);
    __syncthreads();
    if (t < 64) atomicAdd(&out[t], sacc[t] * (1.0f / (float)N));
}

// ---------------- launch ----------------
extern "C" void kernel_launch(void* const* d_in, const int* in_sizes, int n_in,
                              void* d_out, int out_size) {
    const int*   x_ids = (const int*)d_in[0];
    const int*   eidx  = (const int*)d_in[1];
    const float* eattr = (const float*)d_in[2];
    const float* emb   = (const float*)d_in[3];
    const float* W1  = (const float*)d_in[4];
    const float* b1  = (const float*)d_in[5];
    const float* Wu1 = (const float*)d_in[6];
    const float* bu1 = (const float*)d_in[7];
    const float* W2  = (const float*)d_in[8];
    const float* b2  = (const float*)d_in[9];
    const float* Wu2 = (const float*)d_in[10];
    const float* bu2 = (const float*)d_in[11];
    float* out = (float*)d_out;

    int N = in_sizes[0];
    int E = in_sizes[1] / 2;
    int V = in_sizes[3] / D;
    const int* src = eidx;
    const int* dst = eidx + E;

    // CSR build (dst-sorted edges) + zero out
    k_init<<<(N + 255) / 256, 256>>>(out, N);
    k_hist<<<(E + 255) / 256, 256>>>(dst, E);
    int nb = (N + 1023) / 1024;
    k_scan1<<<nb, 256>>>(N);
    k_scan2<<<1, 256>>>(nb);
    k_scan3<<<(N + 1 + 255) / 256, 256>>>(N, E);
    k_scatter<<<(E + 255) / 256, 256>>>(src, dst, eattr, E);

    // embH = emb @ Wx1^T + b1; then X0 = emb[ids], H1 = embH[ids]
    k_embH<<<V, 64>>>(emb, W1, b1, V);
    k_gather<<<(N * 16 + 255) / 256, 256>>>(x_ids, emb, N);

    const int UPD = 1184;
    const int AGG = 2048;

    // round 1
    k_agg<<<AGG, 256>>>(W1, N);                       // Y1 = X0 + agg(relu(H1[src] + We1@ea))
    k_upd<<<UPD, 256>>>(Wu1, bu1, W2, b2, N);         // X1 = relu(Y1@Wu1+bu1); H2 = X1@Wx2^T + b2

    // round 2
    k_agg<<<AGG, 256>>>(W2, N);                       // Y2 = X1 + agg(relu(H2[src] + We2@ea))
    k_final<<<UPD, 256>>>(Wu2, bu2, out, N);          // out = mean(relu(Y2@Wu2+bu2))
}

// round 4
// speedup vs baseline: 1.8004x; 1.1718x over previous
#include <cuda_runtime.h>
#include <cuda_fp16.h>

#define D 64
#define MAXN 100000
#define MAXE 1600000
#define MAXV 1024

typedef unsigned long long ull;

// ---------------- f32x2 packed helpers (Blackwell) ----------------
__device__ __forceinline__ ull d_pack(float lo, float hi) {
    ull r; asm("mov.b64 %0, {%1, %2};" : "=l"(r) : "f"(lo), "f"(hi)); return r;
}
__device__ __forceinline__ float2 d_unpack(ull v) {
    float2 r; asm("mov.b64 {%0, %1}, %2;" : "=f"(r.x), "=f"(r.y) : "l"(v)); return r;
}
__device__ __forceinline__ ull d_dup(float v) {
    ull r; asm("mov.b64 %0, {%1, %1};" : "=l"(r) : "f"(v)); return r;
}
__device__ __forceinline__ ull d_fma2(ull a, ull b, ull c) {
    ull d; asm("fma.rn.f32x2 %0, %1, %2, %3;" : "=l"(d) : "l"(a), "l"(b), "l"(c)); return d;
}

// ---------------- static scratch ----------------
__device__ int     g_rowptr[MAXN + 1];
__device__ int     g_cursor[MAXN];
__device__ int     g_ssrc[MAXE];           // src ids, dst-sorted
__device__ float4  g_sea[MAXE];            // edge_attr, dst-sorted
__device__ float   g_X[MAXN * D];          // node features (fp32)
__device__ __half2 g_Ha[MAXN * 32];        // H buffer A (fp16, bias folded)
__device__ __half2 g_Hb[MAXN * 32];        // H buffer B
__device__ float   g_embH[MAXV * D];       // emb @ Wx1^T + b1
__device__ int     g_bsums[256];

// ---------------- kA: zero cursor + zero out + embH ----------------
__global__ void k_init(const float* __restrict__ emb, const float* __restrict__ W1,
                       const float* __restrict__ b1, float* __restrict__ out, int N, int V) {
    int b = blockIdx.x, t = threadIdx.x;
    int base = b * 1024 + t * 4;
#pragma unroll
    for (int j = 0; j < 4; j++)
        if (base + j < N) g_cursor[base + j] = 0;
    if (b == 0 && t < 64) out[t] = 0.0f;
    if (b < V && t < 64) {
        const float* er = emb + b * D;
        const float* wr = W1 + t * 68;
        float acc = b1[t];
#pragma unroll 16
        for (int j = 0; j < D; j++) acc = fmaf(er[j], wr[j], acc);
        g_embH[b * D + t] = acc;
    }
}

// ---------------- kB: histogram of dst ----------------
__global__ void k_hist(const int* __restrict__ dst, int E) {
    int e = blockIdx.x * blockDim.x + threadIdx.x;
    if (e < E) atomicAdd(&g_cursor[dst[e]], 1);
}

// ---------------- kC: per-1024-chunk exclusive scan + chunk sums ----------------
__global__ void k_scan1(int N) {
    __shared__ int s[256];
    int t = threadIdx.x;
    int base = blockIdx.x * 1024 + t * 4;
    int v0 = (base + 0 < N) ? g_cursor[base + 0] : 0;
    int v1 = (base + 1 < N) ? g_cursor[base + 1] : 0;
    int v2 = (base + 2 < N) ? g_cursor[base + 2] : 0;
    int v3 = (base + 3 < N) ? g_cursor[base + 3] : 0;
    int tsum = v0 + v1 + v2 + v3;
    s[t] = tsum;
    __syncthreads();
    for (int off = 1; off < 256; off <<= 1) {
        int x = (t >= off) ? s[t - off] : 0;
        __syncthreads();
        s[t] += x;
        __syncthreads();
    }
    int excl = s[t] - tsum;
    if (t == 255) g_bsums[blockIdx.x] = s[255];
    if (base + 0 < N) g_rowptr[base + 0] = excl;
    if (base + 1 < N) g_rowptr[base + 1] = excl + v0;
    if (base + 2 < N) g_rowptr[base + 2] = excl + v0 + v1;
    if (base + 3 < N) g_rowptr[base + 3] = excl + v0 + v1 + v2;
}

// ---------------- kD: apply chunk offsets (block-sum prefix recomputed inline) ----------------
__global__ void k_scan3(int N, int E, int nb) {
    __shared__ int s[256];
    int b = blockIdx.x, t = threadIdx.x;
    s[t] = (t < nb && t < b) ? g_bsums[t] : 0;
    __syncthreads();
    for (int off = 128; off > 0; off >>= 1) {
        if (t < off) s[t] += s[t + off];
        __syncthreads();
    }
    int boff = s[0];
    int base = b * 1024 + t * 4;
#pragma unroll
    for (int j = 0; j < 4; j++) {
        int i = base + j;
        if (i < N) {
            int r = g_rowptr[i] + boff;
            g_rowptr[i] = r;
            g_cursor[i] = r;
        }
    }
    if (b == 0 && t == 0) g_rowptr[N] = E;
}

// ---------------- kE: scatter edges (atomic cursor) + gather X0/H1 ----------------
__global__ void k_scatter_gather(const int* __restrict__ src, const int* __restrict__ dst,
                                 const float* __restrict__ ea, const int* __restrict__ ids,
                                 const float* __restrict__ emb, int E, int N, int SB) {
    int b = blockIdx.x;
    if (b < SB) {
        int e = b * 256 + threadIdx.x;
        if (e < E) {
            int p = atomicAdd(&g_cursor[dst[e]], 1);
            g_ssrc[p] = src[e];
            g_sea[p]  = *reinterpret_cast<const float4*>(ea + 4 * (size_t)e);
        }
    } else {
        int i = (b - SB) * 256 + threadIdx.x;
        if (i < N * 16) {
            int n = i >> 4, c = i & 15;
            int id = ids[n];
            reinterpret_cast<float4*>(g_X)[i] = reinterpret_cast<const float4*>(emb)[id * 16 + c];
            float4 h4 = reinterpret_cast<const float4*>(g_embH)[id * 16 + c];
            g_Ha[n * 32 + 2 * c]     = __floats2half2_rn(h4.x, h4.y);
            g_Ha[n * 32 + 2 * c + 1] = __floats2half2_rn(h4.z, h4.w);
        }
    }
}

// ---------------- fused round 1: agg + update-matvec + next-H matvec ----------------
// Y[n] = X0[n] + sum relu(Ha[src] + We1@ea)   (biases of msg MLP folded into H)
// X1[n] = relu(Y@Wu1^T + bu1);  Hb[n] = X1@Wx2^T + b2
__global__ void __launch_bounds__(256) k_round1(const float* __restrict__ W1,
                                                const float* __restrict__ Wu, const float* __restrict__ bu,
                                                const float* __restrict__ Wn, const float* __restrict__ bn,
                                                int N) {
    __shared__ __align__(16) float Wus[4096];          // Wus[j*64+i] = Wu[i][j]
    __shared__ __align__(16) float Wns[4096];          // Wns[j*64+i] = Wn[i][j] (cols 0..63)
    __shared__ __align__(16) float yst[8][4][128];     // per-warp staged y, value-duplicated pairs
    int t = threadIdx.x;
    for (int idx = t; idx < 4096; idx += 256) {
        int i = idx >> 6, j = idx & 63;
        Wus[j * 64 + i] = Wu[i * 64 + j];
        Wns[j * 64 + i] = Wn[i * 68 + j];
    }
    __syncthreads();

    int lane = t & 31, w = t >> 5;
    // packed edge-weight pairs: wp_c = (We[2l][c], We[2l+1][c])
    float4 wa = *reinterpret_cast<const float4*>(W1 + (2 * lane) * 68 + 64);
    float4 wb = *reinterpret_cast<const float4*>(W1 + (2 * lane + 1) * 68 + 64);
    ull wp0 = d_pack(wa.x, wb.x), wp1 = d_pack(wa.y, wb.y);
    ull wp2 = d_pack(wa.z, wb.z), wp3 = d_pack(wa.w, wb.w);
    float bu0 = bu[2 * lane], bu1 = bu[2 * lane + 1];
    float bn0 = bn[2 * lane], bn1 = bn[2 * lane + 1];

    int gw = blockIdx.x * 8 + w;
    int nw = gridDim.x * 8;
    int ng = (N + 3) >> 2;
    for (int g = gw; g < ng; g += nw) {
        int n0 = g * 4;
        // --- phase 1: aggregate 4 nodes ---
        for (int n = 0; n < 4; n++) {
            int nn = n0 + n;
            float2 acc = make_float2(0.0f, 0.0f);
            if (nn < N) {
                acc = *reinterpret_cast<const float2*>(g_X + nn * D + 2 * lane);
                int k0 = g_rowptr[nn], k1 = g_rowptr[nn + 1];
#pragma unroll 4
                for (int k = k0; k < k1; k++) {
                    int s = g_ssrc[k];
                    float4 ea = g_sea[k];
                    float2 hv = __half22float2(g_Ha[s * 32 + lane]);
                    ull m2 = d_pack(hv.x, hv.y);
                    m2 = d_fma2(d_dup(ea.x), wp0, m2);
                    m2 = d_fma2(d_dup(ea.y), wp1, m2);
                    m2 = d_fma2(d_dup(ea.z), wp2, m2);
                    m2 = d_fma2(d_dup(ea.w), wp3, m2);
                    float2 m = d_unpack(m2);
                    acc.x += fmaxf(m.x, 0.0f);
                    acc.y += fmaxf(m.y, 0.0f);
                }
            }
            *reinterpret_cast<float2*>(&yst[w][n][4 * lane])     = make_float2(acc.x, acc.x);
            *reinterpret_cast<float2*>(&yst[w][n][4 * lane + 2]) = make_float2(acc.y, acc.y);
        }
        __syncwarp();
        // --- phase 2: X1 = relu(Y@Wu^T + bu) ---
        ull a2[4] = {0ull, 0ull, 0ull, 0ull};
#pragma unroll 8
        for (int jj = 0; jj < 32; jj++) {
            ull w0 = *reinterpret_cast<const ull*>(&Wus[(2 * jj) * 64 + 2 * lane]);
            ull w1 = *reinterpret_cast<const ull*>(&Wus[(2 * jj + 1) * 64 + 2 * lane]);
#pragma unroll
            for (int n = 0; n < 4; n++) {
                ull xa = *reinterpret_cast<const ull*>(&yst[w][n][4 * jj]);
                ull xb = *reinterpret_cast<const ull*>(&yst[w][n][4 * jj + 2]);
                a2[n] = d_fma2(xa, w0, a2[n]);
                a2[n] = d_fma2(xb, w1, a2[n]);
            }
        }
        __syncwarp();
        float2 xr[4];
#pragma unroll
        for (int n = 0; n < 4; n++) {
            float2 a = d_unpack(a2[n]);
            a.x = fmaxf(a.x + bu0, 0.0f);
            a.y = fmaxf(a.y + bu1, 0.0f);
            xr[n] = a;
            int nn = n0 + n;
            if (nn < N) *reinterpret_cast<float2*>(g_X + nn * D + 2 * lane) = a;
            *reinterpret_cast<float2*>(&yst[w][n][4 * lane])     = make_float2(a.x, a.x);
            *reinterpret_cast<float2*>(&yst[w][n][4 * lane + 2]) = make_float2(a.y, a.y);
        }
        __syncwarp();
        // --- phase 3: Hb = X1@Wn^T + bn ---
        ull h2[4] = {0ull, 0ull, 0ull, 0ull};
#pragma unroll 8
        for (int jj = 0; jj < 32; jj++) {
            ull w0 = *reinterpret_cast<const ull*>(&Wns[(2 * jj) * 64 + 2 * lane]);
            ull w1 = *reinterpret_cast<const ull*>(&Wns[(2 * jj + 1) * 64 + 2 * lane]);
#pragma unroll
            for (int n = 0; n < 4; n++) {
                ull xa = *reinterpret_cast<const ull*>(&yst[w][n][4 * jj]);
                ull xb = *reinterpret_cast<const ull*>(&yst[w][n][4 * jj + 2]);
                h2[n] = d_fma2(xa, w0, h2[n]);
                h2[n] = d_fma2(xb, w1, h2[n]);
            }
        }
        __syncwarp();
#pragma unroll
        for (int n = 0; n < 4; n++) {
            float2 h = d_unpack(h2[n]);
            int nn = n0 + n;
            if (nn < N) g_Hb[nn * 32 + lane] = __floats2half2_rn(h.x + bn0, h.y + bn1);
        }
    }
}

// ---------------- fused round 2: agg + final matvec + mean ----------------
__global__ void __launch_bounds__(256) k_round2(const float* __restrict__ W2,
                                                const float* __restrict__ Wu, const float* __restrict__ bu,
                                                float* __restrict__ out, int N) {
    __shared__ __align__(16) float Wus[4096];
    __shared__ __align__(16) float yst[8][4][128];
    __shared__ float sacc[64];
    int t = threadIdx.x;
    for (int idx = t; idx < 4096; idx += 256) {
        int i = idx >> 6, j = idx & 63;
        Wus[j * 64 + i] = Wu[i * 64 + j];
    }
    if (t < 64) sacc[t] = 0.0f;
    __syncthreads();

    int lane = t & 31, w = t >> 5;
    float4 wa = *reinterpret_cast<const float4*>(W2 + (2 * lane) * 68 + 64);
    float4 wb = *reinterpret_cast<const float4*>(W2 + (2 * lane + 1) * 68 + 64);
    ull wp0 = d_pack(wa.x, wb.x), wp1 = d_pack(wa.y, wb.y);
    ull wp2 = d_pack(wa.z, wb.z), wp3 = d_pack(wa.w, wb.w);
    float bu0 = bu[2 * lane], bu1 = bu[2 * lane + 1];
    float2 tot = make_float2(0.0f, 0.0f);

    int gw = blockIdx.x * 8 + w;
    int nw = gridDim.x * 8;
    int ng = (N + 3) >> 2;
    for (int g = gw; g < ng; g += nw) {
        int n0 = g * 4;
        for (int n = 0; n < 4; n++) {
            int nn = n0 + n;
            float2 acc = make_float2(0.0f, 0.0f);
            if (nn < N) {
                acc = *reinterpret_cast<const float2*>(g_X + nn * D + 2 * lane);
                int k0 = g_rowptr[nn], k1 = g_rowptr[nn + 1];
#pragma unroll 4
                for (int k = k0; k < k1; k++) {
                    int s = g_ssrc[k];
                    float4 ea = g_sea[k];
                    float2 hv = __half22float2(g_Hb[s * 32 + lane]);
                    ull m2 = d_pack(hv.x, hv.y);
                    m2 = d_fma2(d_dup(ea.x), wp0, m2);
                    m2 = d_fma2(d_dup(ea.y), wp1, m2);
                    m2 = d_fma2(d_dup(ea.z), wp2, m2);
                    m2 = d_fma2(d_dup(ea.w), wp3, m2);
                    float2 m = d_unpack(m2);
                    acc.x += fmaxf(m.x, 0.0f);
                    acc.y += fmaxf(m.y, 0.0f);
                }
            }
            *reinterpret_cast<float2*>(&yst[w][n][4 * lane])     = make_float2(acc.x, acc.x);
            *reinterpret_cast<float2*>(&yst[w][n][4 * lane + 2]) = make_float2(acc.y, acc.y);
        }
        __syncwarp();
        ull a2[4] = {0ull, 0ull, 0ull, 0ull};
#pragma unroll 8
        for (int jj = 0; jj < 32; jj++) {
            ull w0 = *reinterpret_cast<const ull*>(&Wus[(2 * jj) * 64 + 2 * lane]);
            ull w1 = *reinterpret_cast<const ull*>(&Wus[(2 * jj + 1) * 64 + 2 * lane]);
#pragma unroll
            for (int n = 0; n < 4; n++) {
                ull xa = *reinterpret_cast<const ull*>(&yst[w][n][4 * jj]);
                ull xb = *reinterpret_cast<const ull*>(&yst[w][n][4 * jj + 2]);
                a2[n] = d_fma2(xa, w0, a2[n]);
                a2[n] = d_fma2(xb, w1, a2[n]);
            }
        }
        __syncwarp();
#pragma unroll
        for (int n = 0; n < 4; n++) {
            int nn = n0 + n;
            if (nn < N) {
                float2 a = d_unpack(a2[n]);
                tot.x += fmaxf(a.x + bu0, 0.0f);
                tot.y += fmaxf(a.y + bu1, 0.0f);
            }
        }
    }
    atomicAdd(&sacc[2 * lane], tot.x);
    atomicAdd(&sacc[2 * lane + 1], tot.y);
    __syncthreads();
    if (t < 64) atomicAdd(&out[t], sacc[t] * (1.0f / (float)N));
}

// ---------------- launch ----------------
extern "C" void kernel_launch(void* const* d_in, const int* in_sizes, int n_in,
                              void* d_out, int out_size) {
    const int*   x_ids = (const int*)d_in[0];
    const int*   eidx  = (const int*)d_in[1];
    const float* eattr = (const float*)d_in[2];
    const float* emb   = (const float*)d_in[3];
    const float* W1  = (const float*)d_in[4];
    const float* b1  = (const float*)d_in[5];
    const float* Wu1 = (const float*)d_in[6];
    const float* bu1 = (const float*)d_in[7];
    const float* W2  = (const float*)d_in[8];
    const float* b2  = (const float*)d_in[9];
    const float* Wu2 = (const float*)d_in[10];
    const float* bu2 = (const float*)d_in[11];
    float* out = (float*)d_out;

    int N = in_sizes[0];
    int E = in_sizes[1] / 2;
    int V = in_sizes[3] / D;
    const int* src = eidx;
    const int* dst = eidx + E;

    int nb = (N + 1023) / 1024;
    int gA = nb > V ? nb : V;
    int SB = (E + 255) / 256;
    int GB = (N * 16 + 255) / 256;

    k_init<<<gA, 256>>>(emb, W1, b1, out, N, V);                      // cursor=0, out=0, embH
    k_hist<<<(E + 255) / 256, 256>>>(dst, E);
    k_scan1<<<nb, 256>>>(N);
    k_scan3<<<nb, 256>>>(N, E, nb);
    k_scatter_gather<<<SB + GB, 256>>>(src, dst, eattr, x_ids, emb, E, N, SB);

    k_round1<<<592, 256>>>(W1, Wu1, bu1, W2, b2, N);
    k_round2<<<592, 256>>>(W2, Wu2, bu2, out, N);
}

// round 5
// speedup vs baseline: 1.9786x; 1.0990x over previous
#include <cuda_runtime.h>
#include <cuda_fp16.h>

#define D 64
#define MAXN 100000
#define MAXE 1600000
#define MAXV 1024

typedef unsigned long long ull;

// ---------------- f32x2 packed helpers (Blackwell) ----------------
__device__ __forceinline__ ull d_pack(float lo, float hi) {
    ull r; asm("mov.b64 %0, {%1, %2};" : "=l"(r) : "f"(lo), "f"(hi)); return r;
}
__device__ __forceinline__ float2 d_unpack(ull v) {
    float2 r; asm("mov.b64 {%0, %1}, %2;" : "=f"(r.x), "=f"(r.y) : "l"(v)); return r;
}
__device__ __forceinline__ ull d_dup(float v) {
    ull r; asm("mov.b64 %0, {%1, %1};" : "=l"(r) : "f"(v)); return r;
}
__device__ __forceinline__ ull d_fma2(ull a, ull b, ull c) {
    ull d; asm("fma.rn.f32x2 %0, %1, %2, %3;" : "=l"(d) : "l"(a), "l"(b), "l"(c)); return d;
}

// ---------------- static scratch ----------------
__device__ int     g_rowptr[MAXN + 1];
__device__ int     g_cursor[MAXN];
__device__ int     g_ssrc[MAXE];           // src ids, dst-sorted
__device__ float4  g_sea[MAXE];            // edge_attr, dst-sorted
__device__ float   g_X[MAXN * D];          // node features (fp32)
__device__ __half2 g_Ha[MAXN * 32];        // H buffer A (fp16; index i = dims (2i, 2i+1))
__device__ __half2 g_Hb[MAXN * 32];        // H buffer B
__device__ float   g_embH[MAXV * D];       // emb @ Wx1^T + b1
__device__ int     g_bsums[256];

// ---------------- kA: zero cursor + zero out + embH ----------------
__global__ void k_init(const float* __restrict__ emb, const float* __restrict__ W1,
                       const float* __restrict__ b1, float* __restrict__ out, int N, int V) {
    int b = blockIdx.x, t = threadIdx.x;
    int base = b * 1024 + t * 4;
#pragma unroll
    for (int j = 0; j < 4; j++)
        if (base + j < N) g_cursor[base + j] = 0;
    if (b == 0 && t < 64) out[t] = 0.0f;
    if (b < V && t < 64) {
        const float* er = emb + b * D;
        const float* wr = W1 + t * 68;
        float acc = b1[t];
#pragma unroll 16
        for (int j = 0; j < D; j++) acc = fmaf(er[j], wr[j], acc);
        g_embH[b * D + t] = acc;
    }
}

// ---------------- kB: histogram of dst ----------------
__global__ void k_hist(const int* __restrict__ dst, int E) {
    int e = blockIdx.x * blockDim.x + threadIdx.x;
    if (e < E) atomicAdd(&g_cursor[dst[e]], 1);
}

// ---------------- kC: per-1024-chunk exclusive scan + chunk sums ----------------
__global__ void k_scan1(int N) {
    __shared__ int s[256];
    int t = threadIdx.x;
    int base = blockIdx.x * 1024 + t * 4;
    int v0 = (base + 0 < N) ? g_cursor[base + 0] : 0;
    int v1 = (base + 1 < N) ? g_cursor[base + 1] : 0;
    int v2 = (base + 2 < N) ? g_cursor[base + 2] : 0;
    int v3 = (base + 3 < N) ? g_cursor[base + 3] : 0;
    int tsum = v0 + v1 + v2 + v3;
    s[t] = tsum;
    __syncthreads();
    for (int off = 1; off < 256; off <<= 1) {
        int x = (t >= off) ? s[t - off] : 0;
        __syncthreads();
        s[t] += x;
        __syncthreads();
    }
    int excl = s[t] - tsum;
    if (t == 255) g_bsums[blockIdx.x] = s[255];
    if (base + 0 < N) g_rowptr[base + 0] = excl;
    if (base + 1 < N) g_rowptr[base + 1] = excl + v0;
    if (base + 2 < N) g_rowptr[base + 2] = excl + v0 + v1;
    if (base + 3 < N) g_rowptr[base + 3] = excl + v0 + v1 + v2;
}

// ---------------- kD: apply chunk offsets ----------------
__global__ void k_scan3(int N, int E, int nb) {
    __shared__ int s[256];
    int b = blockIdx.x, t = threadIdx.x;
    s[t] = (t < nb && t < b) ? g_bsums[t] : 0;
    __syncthreads();
    for (int off = 128; off > 0; off >>= 1) {
        if (t < off) s[t] += s[t + off];
        __syncthreads();
    }
    int boff = s[0];
    int base = b * 1024 + t * 4;
#pragma unroll
    for (int j = 0; j < 4; j++) {
        int i = base + j;
        if (i < N) {
            int r = g_rowptr[i] + boff;
            g_rowptr[i] = r;
            g_cursor[i] = r;
        }
    }
    if (b == 0 && t == 0) g_rowptr[N] = E;
}

// ---------------- kE: scatter edges + gather X0/H1 ----------------
__global__ void k_scatter_gather(const int* __restrict__ src, const int* __restrict__ dst,
                                 const float* __restrict__ ea, const int* __restrict__ ids,
                                 const float* __restrict__ emb, int E, int N, int SB) {
    int b = blockIdx.x;
    if (b < SB) {
        int e = b * 256 + threadIdx.x;
        if (e < E) {
            int p = atomicAdd(&g_cursor[dst[e]], 1);
            g_ssrc[p] = src[e];
            g_sea[p]  = *reinterpret_cast<const float4*>(ea + 4 * (size_t)e);
        }
    } else {
        int i = (b - SB) * 256 + threadIdx.x;
        if (i < N * 16) {
            int n = i >> 4, c = i & 15;
            int id = ids[n];
            reinterpret_cast<float4*>(g_X)[i] = reinterpret_cast<const float4*>(emb)[id * 16 + c];
            float4 h4 = reinterpret_cast<const float4*>(g_embH)[id * 16 + c];
            g_Ha[n * 32 + 2 * c]     = __floats2half2_rn(h4.x, h4.y);
            g_Ha[n * 32 + 2 * c + 1] = __floats2half2_rn(h4.z, h4.w);
        }
    }
}

// ======= shared building blocks for the fused round kernels =======

// Fill interleaved weight tile: Wi[jj*64 + 2*lane + q] (ull) = (W[2l][2jj+q], W[2l+1][2jj+q])
// As floats: Wf[jj*128 + lane*4 + q*2 + h] = W[(2*lane+h)*stride + (2*jj+q)]
__device__ __forceinline__ void fill_wint(float* Wf, const float* __restrict__ W, int stride, int t) {
    for (int idx = t; idx < 4096; idx += 256) {
        int jj = idx >> 7, r = idx & 127;
        int l = r >> 2, q = (r >> 1) & 1, h = r & 1;
        Wf[idx] = W[(2 * l + h) * stride + (2 * jj + q)];
    }
}

// matvec: a2[n] = sum over columns of dup-y tile * interleaved W; lane owns dims (2l, 2l+1)
__device__ __forceinline__ void mv64(ull* a2, const ull* Wi, const float* ydn0, int lane) {
#pragma unroll 8
    for (int jj = 0; jj < 32; jj++) {
        longlong2 wv = *reinterpret_cast<const longlong2*>(Wi + jj * 64 + 2 * lane);
#pragma unroll
        for (int n = 0; n < 4; n++) {
            longlong2 xv = *reinterpret_cast<const longlong2*>(ydn0 + n * 128 + 4 * jj);
            a2[n] = d_fma2((ull)xv.x, (ull)wv.x, a2[n]);
            a2[n] = d_fma2((ull)xv.y, (ull)wv.y, a2[n]);
        }
    }
}

// half-warp agg for node pair (n0+2p, n0+2p+1); lane owns dims 4hl..4hl+3 of its half's node.
// Writes duplicated-pair layout into yd row (n = 2p+half).
__device__ __forceinline__ void agg_pair(float* ydrow_base, const __half2* __restrict__ H,
                                         const ull* wpa, const ull* wpb,
                                         int n0, int p, int half, int hl, int N) {
    int nn = n0 + 2 * p + half;
    bool valid = nn < N;
    int nc = valid ? nn : 0;
    int k0 = g_rowptr[nc], k1 = g_rowptr[nc + 1];
    int len = valid ? (k1 - k0) : 0;
    int maxlen = __reduce_max_sync(0xffffffffu, len);
    float a0 = 0.f, a1 = 0.f, a2v = 0.f, a3 = 0.f;
    if (valid) {
        float4 x0 = *reinterpret_cast<const float4*>(g_X + nn * D + 4 * hl);
        a0 = x0.x; a1 = x0.y; a2v = x0.z; a3 = x0.w;
    }
    for (int i = 0; i < maxlen; i++) {
        int k = k0 + i;
        bool act = (i < len);
        int kk = act ? k : 0;
        int s = g_ssrc[kk];
        float4 ea = g_sea[kk];
        uint2 hv = *reinterpret_cast<const uint2*>(H + s * 32 + 2 * hl);
        float2 h0 = __half22float2(*reinterpret_cast<const __half2*>(&hv.x));
        float2 h1 = __half22float2(*reinterpret_cast<const __half2*>(&hv.y));
        ull m0 = d_pack(h0.x, h0.y);
        ull m1 = d_pack(h1.x, h1.y);
        ull e0 = d_dup(ea.x), e1 = d_dup(ea.y), e2 = d_dup(ea.z), e3 = d_dup(ea.w);
        m0 = d_fma2(e0, wpa[0], m0); m0 = d_fma2(e1, wpa[1], m0);
        m0 = d_fma2(e2, wpa[2], m0); m0 = d_fma2(e3, wpa[3], m0);
        m1 = d_fma2(e0, wpb[0], m1); m1 = d_fma2(e1, wpb[1], m1);
        m1 = d_fma2(e2, wpb[2], m1); m1 = d_fma2(e3, wpb[3], m1);
        if (act) {
            float2 f0 = d_unpack(m0), f1 = d_unpack(m1);
            a0 += fmaxf(f0.x, 0.0f); a1 += fmaxf(f0.y, 0.0f);
            a2v += fmaxf(f1.x, 0.0f); a3 += fmaxf(f1.y, 0.0f);
        }
    }
    float* row = ydrow_base + (2 * p + half) * 128 + 8 * hl;
    *reinterpret_cast<float4*>(row)     = make_float4(a0, a0, a1, a1);
    *reinterpret_cast<float4*>(row + 4) = make_float4(a2v, a2v, a3, a3);
}

// ---------------- fused round 1 ----------------
__global__ void __launch_bounds__(256) k_round1(const float* __restrict__ W1,
                                                const float* __restrict__ Wu, const float* __restrict__ bu,
                                                const float* __restrict__ Wn, const float* __restrict__ bn,
                                                int N) {
    __shared__ __align__(16) ull Wus[2048];
    __shared__ __align__(16) ull Wns[2048];
    __shared__ __align__(16) float yd[8][4 * 128];
    int t = threadIdx.x;
    fill_wint(reinterpret_cast<float*>(Wus), Wu, 64, t);
    fill_wint(reinterpret_cast<float*>(Wns), Wn, 68, t);
    __syncthreads();

    int lane = t & 31, w = t >> 5;
    int half = lane >> 4, hl = lane & 15;

    // agg edge-weight pairs for this lane's 4 dims (cols 64..67 of W1)
    float4 q0 = *reinterpret_cast<const float4*>(W1 + (4 * hl) * 68 + 64);
    float4 q1 = *reinterpret_cast<const float4*>(W1 + (4 * hl + 1) * 68 + 64);
    float4 q2 = *reinterpret_cast<const float4*>(W1 + (4 * hl + 2) * 68 + 64);
    float4 q3 = *reinterpret_cast<const float4*>(W1 + (4 * hl + 3) * 68 + 64);
    ull wpa[4] = {d_pack(q0.x, q1.x), d_pack(q0.y, q1.y), d_pack(q0.z, q1.z), d_pack(q0.w, q1.w)};
    ull wpb[4] = {d_pack(q2.x, q3.x), d_pack(q2.y, q3.y), d_pack(q2.z, q3.z), d_pack(q2.w, q3.w)};

    float bu0 = bu[2 * lane], bu1 = bu[2 * lane + 1];
    float bn0 = bn[2 * lane], bn1 = bn[2 * lane + 1];

    int gw = blockIdx.x * 8 + w;
    int nw = gridDim.x * 8;
    int ng = (N + 3) >> 2;
    for (int g = gw; g < ng; g += nw) {
        int n0 = g * 4;
        agg_pair(yd[w], g_Ha, wpa, wpb, n0, 0, half, hl, N);
        agg_pair(yd[w], g_Ha, wpa, wpb, n0, 1, half, hl, N);
        __syncwarp();
        // X1 = relu(Y@Wu^T + bu)
        ull a2[4] = {0ull, 0ull, 0ull, 0ull};
        mv64(a2, Wus, yd[w], lane);
        __syncwarp();
#pragma unroll
        for (int n = 0; n < 4; n++) {
            float2 a = d_unpack(a2[n]);
            a.x = fmaxf(a.x + bu0, 0.0f);
            a.y = fmaxf(a.y + bu1, 0.0f);
            int nn = n0 + n;
            if (nn < N) *reinterpret_cast<float2*>(g_X + nn * D + 2 * lane) = a;
            *reinterpret_cast<ull*>(&yd[w][n * 128 + 4 * lane])     = d_dup(a.x);
            *reinterpret_cast<ull*>(&yd[w][n * 128 + 4 * lane + 2]) = d_dup(a.y);
        }
        __syncwarp();
        // Hb = X1@Wn^T + bn
        ull h2[4] = {0ull, 0ull, 0ull, 0ull};
        mv64(h2, Wns, yd[w], lane);
        __syncwarp();
#pragma unroll
        for (int n = 0; n < 4; n++) {
            float2 h = d_unpack(h2[n]);
            int nn = n0 + n;
            if (nn < N) g_Hb[nn * 32 + lane] = __floats2half2_rn(h.x + bn0, h.y + bn1);
        }
    }
}

// ---------------- fused round 2: agg + final matvec + mean ----------------
__global__ void __launch_bounds__(256) k_round2(const float* __restrict__ W2,
                                                const float* __restrict__ Wu, const float* __restrict__ bu,
                                                float* __restrict__ out, int N) {
    __shared__ __align__(16) ull Wus[2048];
    __shared__ __align__(16) float yd[8][4 * 128];
    __shared__ float sacc[64];
    int t = threadIdx.x;
    fill_wint(reinterpret_cast<float*>(Wus), Wu, 64, t);
    if (t < 64) sacc[t] = 0.0f;
    __syncthreads();

    int lane = t & 31, w = t >> 5;
    int half = lane >> 4, hl = lane & 15;

    float4 q0 = *reinterpret_cast<const float4*>(W2 + (4 * hl) * 68 + 64);
    float4 q1 = *reinterpret_cast<const float4*>(W2 + (4 * hl + 1) * 68 + 64);
    float4 q2 = *reinterpret_cast<const float4*>(W2 + (4 * hl + 2) * 68 + 64);
    float4 q3 = *reinterpret_cast<const float4*>(W2 + (4 * hl + 3) * 68 + 64);
    ull wpa[4] = {d_pack(q0.x, q1.x), d_pack(q0.y, q1.y), d_pack(q0.z, q1.z), d_pack(q0.w, q1.w)};
    ull wpb[4] = {d_pack(q2.x, q3.x), d_pack(q2.y, q3.y), d_pack(q2.z, q3.z), d_pack(q2.w, q3.w)};

    float bu0 = bu[2 * lane], bu1 = bu[2 * lane + 1];
    float2 tot = make_float2(0.0f, 0.0f);

    int gw = blockIdx.x * 8 + w;
    int nw = gridDim.x * 8;
    int ng = (N + 3) >> 2;
    for (int g = gw; g < ng; g += nw) {
        int n0 = g * 4;
        agg_pair(yd[w], g_Hb, wpa, wpb, n0, 0, half, hl, N);
        agg_pair(yd[w], g_Hb, wpa, wpb, n0, 1, half, hl, N);
        __syncwarp();
        ull a2[4] = {0ull, 0ull, 0ull, 0ull};
        mv64(a2, Wus, yd[w], lane);
        __syncwarp();
#pragma unroll
        for (int n = 0; n < 4; n++) {
            int nn = n0 + n;
            if (nn < N) {
                float2 a = d_unpack(a2[n]);
                tot.x += fmaxf(a.x + bu0, 0.0f);
                tot.y += fmaxf(a.y + bu1, 0.0f);
            }
        }
    }
    atomicAdd(&sacc[2 * lane], tot.x);
    atomicAdd(&sacc[2 * lane + 1], tot.y);
    __syncthreads();
    if (t < 64) atomicAdd(&out[t], sacc[t] * (1.0f / (float)N));
}

// ---------------- launch ----------------
extern "C" void kernel_launch(void* const* d_in, const int* in_sizes, int n_in,
                              void* d_out, int out_size) {
    const int*   x_ids = (const int*)d_in[0];
    const int*   eidx  = (const int*)d_in[1];
    const float* eattr = (const float*)d_in[2];
    const float* emb   = (const float*)d_in[3];
    const float* W1  = (const float*)d_in[4];
    const float* b1  = (const float*)d_in[5];
    const float* Wu1 = (const float*)d_in[6];
    const float* bu1 = (const float*)d_in[7];
    const float* W2  = (const float*)d_in[8];
    const float* b2  = (const float*)d_in[9];
    const float* Wu2 = (const float*)d_in[10];
    const float* bu2 = (const float*)d_in[11];
    float* out = (float*)d_out;

    int N = in_sizes[0];
    int E = in_sizes[1] / 2;
    int V = in_sizes[3] / D;
    const int* src = eidx;
    const int* dst = eidx + E;

    int nb = (N + 1023) / 1024;
    int gA = nb > V ? nb : V;
    int SB = (E + 255) / 256;
    int GB = (N * 16 + 255) / 256;

    k_init<<<gA, 256>>>(emb, W1, b1, out, N, V);
    k_hist<<<(E + 255) / 256, 256>>>(dst, E);
    k_scan1<<<nb, 256>>>(N);
    k_scan3<<<nb, 256>>>(N, E, nb);
    k_scatter_gather<<<SB + GB, 256>>>(src, dst, eattr, x_ids, emb, E, N, SB);

    k_round1<<<592, 256>>>(W1, Wu1, bu1, W2, b2, N);
    k_round2<<<592, 256>>>(W2, Wu2, bu2, out, N);
}

// round 6
// speedup vs baseline: 2.0173x; 1.0196x over previous
#include <cuda_runtime.h>
#include <cuda_fp16.h>

#define D 64
#define MAXN 100000
#define MAXE 1600000
#define MAXV 1024

typedef unsigned long long ull;

// ---------------- f32x2 packed helpers (Blackwell) ----------------
__device__ __forceinline__ ull d_pack(float lo, float hi) {
    ull r; asm("mov.b64 %0, {%1, %2};" : "=l"(r) : "f"(lo), "f"(hi)); return r;
}
__device__ __forceinline__ float2 d_unpack(ull v) {
    float2 r; asm("mov.b64 {%0, %1}, %2;" : "=f"(r.x), "=f"(r.y) : "l"(v)); return r;
}
__device__ __forceinline__ ull d_dup(float v) {
    ull r; asm("mov.b64 %0, {%1, %1};" : "=l"(r) : "f"(v)); return r;
}
__device__ __forceinline__ ull d_fma2(ull a, ull b, ull c) {
    ull d; asm("fma.rn.f32x2 %0, %1, %2, %3;" : "=l"(d) : "l"(a), "l"(b), "l"(c)); return d;
}

// ---------------- static scratch ----------------
__device__ int     g_rowptr[MAXN + 1];
__device__ int     g_cursor[MAXN];
__device__ uint4   g_edge[MAXE];           // {src, ea01(half2), ea23(half2), pad}, dst-sorted
__device__ float   g_X[MAXN * D];          // node features (fp32)
__device__ __half2 g_Ha[MAXN * 32];        // H buffer A (fp16; index i = dims (2i, 2i+1))
__device__ __half2 g_Hb[MAXN * 32];        // H buffer B
__device__ float   g_embH[MAXV * D];       // emb @ Wx1^T + b1
__device__ int     g_bsums[256];

// ---------------- kA: zero cursor + zero out + embH ----------------
__global__ void k_init(const float* __restrict__ emb, const float* __restrict__ W1,
                       const float* __restrict__ b1, float* __restrict__ out, int N, int V) {
    int b = blockIdx.x, t = threadIdx.x;
    int base = b * 1024 + t * 4;
#pragma unroll
    for (int j = 0; j < 4; j++)
        if (base + j < N) g_cursor[base + j] = 0;
    if (b == 0 && t < 64) out[t] = 0.0f;
    if (b < V && t < 64) {
        const float* er = emb + b * D;
        const float* wr = W1 + t * 68;
        float acc = b1[t];
#pragma unroll 16
        for (int j = 0; j < D; j++) acc = fmaf(er[j], wr[j], acc);
        g_embH[b * D + t] = acc;
    }
}

// ---------------- kB: histogram of dst ----------------
__global__ void k_hist(const int* __restrict__ dst, int E) {
    int e = blockIdx.x * blockDim.x + threadIdx.x;
    if (e < E) atomicAdd(&g_cursor[dst[e]], 1);
}

// ---------------- kC: per-1024-chunk exclusive scan + chunk sums ----------------
__global__ void k_scan1(int N) {
    __shared__ int s[256];
    int t = threadIdx.x;
    int base = blockIdx.x * 1024 + t * 4;
    int v0 = (base + 0 < N) ? g_cursor[base + 0] : 0;
    int v1 = (base + 1 < N) ? g_cursor[base + 1] : 0;
    int v2 = (base + 2 < N) ? g_cursor[base + 2] : 0;
    int v3 = (base + 3 < N) ? g_cursor[base + 3] : 0;
    int tsum = v0 + v1 + v2 + v3;
    s[t] = tsum;
    __syncthreads();
    for (int off = 1; off < 256; off <<= 1) {
        int x = (t >= off) ? s[t - off] : 0;
        __syncthreads();
        s[t] += x;
        __syncthreads();
    }
    int excl = s[t] - tsum;
    if (t == 255) g_bsums[blockIdx.x] = s[255];
    if (base + 0 < N) g_rowptr[base + 0] = excl;
    if (base + 1 < N) g_rowptr[base + 1] = excl + v0;
    if (base + 2 < N) g_rowptr[base + 2] = excl + v0 + v1;
    if (base + 3 < N) g_rowptr[base + 3] = excl + v0 + v1 + v2;
}

// ---------------- kD: apply chunk offsets ----------------
__global__ void k_scan3(int N, int E, int nb) {
    __shared__ int s[256];
    int b = blockIdx.x, t = threadIdx.x;
    s[t] = (t < nb && t < b) ? g_bsums[t] : 0;
    __syncthreads();
    for (int off = 128; off > 0; off >>= 1) {
        if (t < off) s[t] += s[t + off];
        __syncthreads();
    }
    int boff = s[0];
    int base = b * 1024 + t * 4;
#pragma unroll
    for (int j = 0; j < 4; j++) {
        int i = base + j;
        if (i < N) {
            int r = g_rowptr[i] + boff;
            g_rowptr[i] = r;
            g_cursor[i] = r;
        }
    }
    if (b == 0 && t == 0) g_rowptr[N] = E;
}

// ---------------- kE: scatter packed edge records + gather X0/H1 ----------------
__global__ void k_scatter_gather(const int* __restrict__ src, const int* __restrict__ dst,
                                 const float* __restrict__ ea, const int* __restrict__ ids,
                                 const float* __restrict__ emb, int E, int N, int SB) {
    int b = blockIdx.x;
    if (b < SB) {
        int e = b * 256 + threadIdx.x;
        if (e < E) {
            int p = atomicAdd(&g_cursor[dst[e]], 1);
            float4 v = *reinterpret_cast<const float4*>(ea + 4 * (size_t)e);
            __half2 e01 = __floats2half2_rn(v.x, v.y);
            __half2 e23 = __floats2half2_rn(v.z, v.w);
            uint4 rec;
            rec.x = (unsigned)src[e];
            rec.y = *reinterpret_cast<const unsigned*>(&e01);
            rec.z = *reinterpret_cast<const unsigned*>(&e23);
            rec.w = 0u;
            g_edge[p] = rec;
        }
    } else {
        int i = (b - SB) * 256 + threadIdx.x;
        if (i < N * 16) {
            int n = i >> 4, c = i & 15;
            int id = ids[n];
            reinterpret_cast<float4*>(g_X)[i] = reinterpret_cast<const float4*>(emb)[id * 16 + c];
            float4 h4 = reinterpret_cast<const float4*>(g_embH)[id * 16 + c];
            g_Ha[n * 32 + 2 * c]     = __floats2half2_rn(h4.x, h4.y);
            g_Ha[n * 32 + 2 * c + 1] = __floats2half2_rn(h4.z, h4.w);
        }
    }
}

// ======= shared building blocks for the fused round kernels =======

// Fill interleaved weight tile: Wi[jj*64 + 2*lane + q] (ull) = (W[2l][2jj+q], W[2l+1][2jj+q])
__device__ __forceinline__ void fill_wint(float* Wf, const float* __restrict__ W, int stride, int t) {
    for (int idx = t; idx < 4096; idx += 256) {
        int jj = idx >> 7, r = idx & 127;
        int l = r >> 2, q = (r >> 1) & 1, h = r & 1;
        Wf[idx] = W[(2 * l + h) * stride + (2 * jj + q)];
    }
}

// matvec: a2[n] = sum over columns of dup-y tile * interleaved W; lane owns dims (2l, 2l+1)
__device__ __forceinline__ void mv64(ull* a2, const ull* Wi, const float* ydn0, int lane) {
#pragma unroll 8
    for (int jj = 0; jj < 32; jj++) {
        longlong2 wv = *reinterpret_cast<const longlong2*>(Wi + jj * 64 + 2 * lane);
#pragma unroll
        for (int n = 0; n < 4; n++) {
            longlong2 xv = *reinterpret_cast<const longlong2*>(ydn0 + n * 128 + 4 * jj);
            a2[n] = d_fma2((ull)xv.x, (ull)wv.x, a2[n]);
            a2[n] = d_fma2((ull)xv.y, (ull)wv.y, a2[n]);
        }
    }
}

// process one packed edge record for this lane's 4 dims
__device__ __forceinline__ void edge_accum(uint4 rec, uint2 hv,
                                           const ull* wpa, const ull* wpb, bool act,
                                           float& a0, float& a1, float& a2v, float& a3) {
    float2 e01 = __half22float2(*reinterpret_cast<const __half2*>(&rec.y));
    float2 e23 = __half22float2(*reinterpret_cast<const __half2*>(&rec.z));
    float2 h0 = __half22float2(*reinterpret_cast<const __half2*>(&hv.x));
    float2 h1 = __half22float2(*reinterpret_cast<const __half2*>(&hv.y));
    ull m0 = d_pack(h0.x, h0.y);
    ull m1 = d_pack(h1.x, h1.y);
    ull e0 = d_dup(e01.x), e1 = d_dup(e01.y), e2 = d_dup(e23.x), e3 = d_dup(e23.y);
    m0 = d_fma2(e0, wpa[0], m0); m0 = d_fma2(e1, wpa[1], m0);
    m0 = d_fma2(e2, wpa[2], m0); m0 = d_fma2(e3, wpa[3], m0);
    m1 = d_fma2(e0, wpb[0], m1); m1 = d_fma2(e1, wpb[1], m1);
    m1 = d_fma2(e2, wpb[2], m1); m1 = d_fma2(e3, wpb[3], m1);
    if (act) {
        float2 f0 = d_unpack(m0), f1 = d_unpack(m1);
        a0 += fmaxf(f0.x, 0.0f); a1 += fmaxf(f0.y, 0.0f);
        a2v += fmaxf(f1.x, 0.0f); a3 += fmaxf(f1.y, 0.0f);
    }
}

// half-warp agg for node pair (n0+2p, n0+2p+1); lane owns dims 4hl..4hl+3; 2x unrolled (MLP=2)
__device__ __forceinline__ void agg_pair(float* ydrow_base, const __half2* __restrict__ H,
                                         const ull* wpa, const ull* wpb,
                                         int n0, int p, int half, int hl, int N) {
    int nn = n0 + 2 * p + half;
    bool valid = nn < N;
    int nc = valid ? nn : 0;
    int k0 = g_rowptr[nc], k1 = g_rowptr[nc + 1];
    int len = valid ? (k1 - k0) : 0;
    int maxlen = __reduce_max_sync(0xffffffffu, len);
    float a0 = 0.f, a1 = 0.f, a2v = 0.f, a3 = 0.f;
    if (valid) {
        float4 x0 = *reinterpret_cast<const float4*>(g_X + nn * D + 4 * hl);
        a0 = x0.x; a1 = x0.y; a2v = x0.z; a3 = x0.w;
    }
    int i = 0;
    for (; i + 2 <= maxlen; i += 2) {
        bool actA = (i < len), actB = (i + 1 < len);
        uint4 rA = g_edge[actA ? (k0 + i) : 0];
        uint4 rB = g_edge[actB ? (k0 + i + 1) : 0];
        uint2 hvA = *reinterpret_cast<const uint2*>(H + (int)rA.x * 32 + 2 * hl);
        uint2 hvB = *reinterpret_cast<const uint2*>(H + (int)rB.x * 32 + 2 * hl);
        edge_accum(rA, hvA, wpa, wpb, actA, a0, a1, a2v, a3);
        edge_accum(rB, hvB, wpa, wpb, actB, a0, a1, a2v, a3);
    }
    if (i < maxlen) {
        bool act = (i < len);
        uint4 r = g_edge[act ? (k0 + i) : 0];
        uint2 hv = *reinterpret_cast<const uint2*>(H + (int)r.x * 32 + 2 * hl);
        edge_accum(r, hv, wpa, wpb, act, a0, a1, a2v, a3);
    }
    float* row = ydrow_base + (2 * p + half) * 128 + 8 * hl;
    *reinterpret_cast<float4*>(row)     = make_float4(a0, a0, a1, a1);
    *reinterpret_cast<float4*>(row + 4) = make_float4(a2v, a2v, a3, a3);
}

// ---------------- fused round 1 ----------------
__global__ void __launch_bounds__(256, 3) k_round1(const float* __restrict__ W1,
                                                   const float* __restrict__ Wu, const float* __restrict__ bu,
                                                   const float* __restrict__ Wn, const float* __restrict__ bn,
                                                   int N) {
    __shared__ __align__(16) ull Wus[2048];
    __shared__ __align__(16) ull Wns[2048];
    __shared__ __align__(16) float yd[8][4 * 128];
    int t = threadIdx.x;
    fill_wint(reinterpret_cast<float*>(Wus), Wu, 64, t);
    fill_wint(reinterpret_cast<float*>(Wns), Wn, 68, t);
    __syncthreads();

    int lane = t & 31, w = t >> 5;
    int half = lane >> 4, hl = lane & 15;

    float4 q0 = *reinterpret_cast<const float4*>(W1 + (4 * hl) * 68 + 64);
    float4 q1 = *reinterpret_cast<const float4*>(W1 + (4 * hl + 1) * 68 + 64);
    float4 q2 = *reinterpret_cast<const float4*>(W1 + (4 * hl + 2) * 68 + 64);
    float4 q3 = *reinterpret_cast<const float4*>(W1 + (4 * hl + 3) * 68 + 64);
    ull wpa[4] = {d_pack(q0.x, q1.x), d_pack(q0.y, q1.y), d_pack(q0.z, q1.z), d_pack(q0.w, q1.w)};
    ull wpb[4] = {d_pack(q2.x, q3.x), d_pack(q2.y, q3.y), d_pack(q2.z, q3.z), d_pack(q2.w, q3.w)};

    float bu0 = bu[2 * lane], bu1 = bu[2 * lane + 1];
    float bn0 = bn[2 * lane], bn1 = bn[2 * lane + 1];

    int gw = blockIdx.x * 8 + w;
    int nw = gridDim.x * 8;
    int ng = (N + 3) >> 2;
    for (int g = gw; g < ng; g += nw) {
        int n0 = g * 4;
        agg_pair(yd[w], g_Ha, wpa, wpb, n0, 0, half, hl, N);
        agg_pair(yd[w], g_Ha, wpa, wpb, n0, 1, half, hl, N);
        __syncwarp();
        ull a2[4] = {0ull, 0ull, 0ull, 0ull};
        mv64(a2, Wus, yd[w], lane);
        __syncwarp();
#pragma unroll
        for (int n = 0; n < 4; n++) {
            float2 a = d_unpack(a2[n]);
            a.x = fmaxf(a.x + bu0, 0.0f);
            a.y = fmaxf(a.y + bu1, 0.0f);
            int nn = n0 + n;
            if (nn < N) *reinterpret_cast<float2*>(g_X + nn * D + 2 * lane) = a;
            *reinterpret_cast<ull*>(&yd[w][n * 128 + 4 * lane])     = d_dup(a.x);
            *reinterpret_cast<ull*>(&yd[w][n * 128 + 4 * lane + 2]) = d_dup(a.y);
        }
        __syncwarp();
        ull h2[4] = {0ull, 0ull, 0ull, 0ull};
        mv64(h2, Wns, yd[w], lane);
        __syncwarp();
#pragma unroll
        for (int n = 0; n < 4; n++) {
            float2 h = d_unpack(h2[n]);
            int nn = n0 + n;
            if (nn < N) g_Hb[nn * 32 + lane] = __floats2half2_rn(h.x + bn0, h.y + bn1);
        }
    }
}

// ---------------- fused round 2: agg + final matvec + mean ----------------
__global__ void __launch_bounds__(256, 3) k_round2(const float* __restrict__ W2,
                                                   const float* __restrict__ Wu, const float* __restrict__ bu,
                                                   float* __restrict__ out, int N) {
    __shared__ __align__(16) ull Wus[2048];
    __shared__ __align__(16) float yd[8][4 * 128];
    __shared__ float sacc[64];
    int t = threadIdx.x;
    fill_wint(reinterpret_cast<float*>(Wus), Wu, 64, t);
    if (t < 64) sacc[t] = 0.0f;
    __syncthreads();

    int lane = t & 31, w = t >> 5;
    int half = lane >> 4, hl = lane & 15;

    float4 q0 = *reinterpret_cast<const float4*>(W2 + (4 * hl) * 68 + 64);
    float4 q1 = *reinterpret_cast<const float4*>(W2 + (4 * hl + 1) * 68 + 64);
    float4 q2 = *reinterpret_cast<const float4*>(W2 + (4 * hl + 2) * 68 + 64);
    float4 q3 = *reinterpret_cast<const float4*>(W2 + (4 * hl + 3) * 68 + 64);
    ull wpa[4] = {d_pack(q0.x, q1.x), d_pack(q0.y, q1.y), d_pack(q0.z, q1.z), d_pack(q0.w, q1.w)};
    ull wpb[4] = {d_pack(q2.x, q3.x), d_pack(q2.y, q3.y), d_pack(q2.z, q3.z), d_pack(q2.w, q3.w)};

    float bu0 = bu[2 * lane], bu1 = bu[2 * lane + 1];
    float2 tot = make_float2(0.0f, 0.0f);

    int gw = blockIdx.x * 8 + w;
    int nw = gridDim.x * 8;
    int ng = (N + 3) >> 2;
    for (int g = gw; g < ng; g += nw) {
        int n0 = g * 4;
        agg_pair(yd[w], g_Hb, wpa, wpb, n0, 0, half, hl, N);
        agg_pair(yd[w], g_Hb, wpa, wpb, n0, 1, half, hl, N);
        __syncwarp();
        ull a2[4] = {0ull, 0ull, 0ull, 0ull};
        mv64(a2, Wus, yd[w], lane);
        __syncwarp();
#pragma unroll
        for (int n = 0; n < 4; n++) {
            int nn = n0 + n;
            if (nn < N) {
                float2 a = d_unpack(a2[n]);
                tot.x += fmaxf(a.x + bu0, 0.0f);
                tot.y += fmaxf(a.y + bu1, 0.0f);
            }
        }
    }
    atomicAdd(&sacc[2 * lane], tot.x);
    atomicAdd(&sacc[2 * lane + 1], tot.y);
    __syncthreads();
    if (t < 64) atomicAdd(&out[t], sacc[t] * (1.0f / (float)N));
}

// ---------------- launch ----------------
extern "C" void kernel_launch(void* const* d_in, const int* in_sizes, int n_in,
                              void* d_out, int out_size) {
    const int*   x_ids = (const int*)d_in[0];
    const int*   eidx  = (const int*)d_in[1];
    const float* eattr = (const float*)d_in[2];
    const float* emb   = (const float*)d_in[3];
    const float* W1  = (const float*)d_in[4];
    const float* b1  = (const float*)d_in[5];
    const float* Wu1 = (const float*)d_in[6];
    const float* bu1 = (const float*)d_in[7];
    const float* W2  = (const float*)d_in[8];
    const float* b2  = (const float*)d_in[9];
    const float* Wu2 = (const float*)d_in[10];
    const float* bu2 = (const float*)d_in[11];
    float* out = (float*)d_out;

    int N = in_sizes[0];
    int E = in_sizes[1] / 2;
    int V = in_sizes[3] / D;
    const int* src = eidx;
    const int* dst = eidx + E;

    int nb = (N + 1023) / 1024;
    int gA = nb > V ? nb : V;
    int SB = (E + 255) / 256;
    int GB = (N * 16 + 255) / 256;

    k_init<<<gA, 256>>>(emb, W1, b1, out, N, V);
    k_hist<<<(E + 255) / 256, 256>>>(dst, E);
    k_scan1<<<nb, 256>>>(N);
    k_scan3<<<nb, 256>>>(N, E, nb);
    k_scatter_gather<<<SB + GB, 256>>>(src, dst, eattr, x_ids, emb, E, N, SB);

    const int RG = 444;   // 3 blocks/SM x 148 SMs, single wave
    k_round1<<<RG, 256>>>(W1, Wu1, bu1, W2, b2, N);
    k_round2<<<RG, 256>>>(W2, Wu2, bu2, out, N);
}